// round 1
// baseline (speedup 1.0000x reference)
#include <cuda_runtime.h>
#include <cuda_bf16.h>

#define CC 64
#define KK 20
#define TILE 256
#define NMAX (1 << 20)

typedef unsigned long long ull;

// ---------------- device scratch (static; no allocations allowed) -------------
__device__ float  g_h0[(size_t)NMAX * CC];   // 256 MiB scratch: h0 = feat @ W1
__device__ double g_acc[5];                  // segnum, segden, l1, cos, cnt
__device__ double g_sum[CC];
__device__ double g_sumsq[CC];
__device__ float2 g_AB[CC];                  // BN-folded affine: h0*A + B
__device__ float4 g_W2p[CC];                 // W2 rows padded to float4

// ---------------- f32x2 packed math (Blackwell FFMA2) -------------------------
__device__ __forceinline__ ull fma2(ull a, ull b, ull c) {
    ull d;
    asm("fma.rn.f32x2 %0, %1, %2, %3;" : "=l"(d) : "l"(a), "l"(b), "l"(c));
    return d;
}
__device__ __forceinline__ ull bcast2(float x) {
    ull r;
    asm("mov.b64 %0, {%1, %1};" : "=l"(r) : "f"(x));
    return r;
}
__device__ __forceinline__ float2 unpk(ull v) {
    float lo, hi;
    asm("mov.b64 {%0, %1}, %2;" : "=f"(lo), "=f"(hi) : "l"(v));
    return make_float2(lo, hi);
}
__device__ __forceinline__ float wsum(float v) {
#pragma unroll
    for (int o = 16; o > 0; o >>= 1) v += __shfl_down_sync(0xffffffffu, v, o);
    return v;
}

// ---------------- smem layouts (floats) ---------------------------------------
// pass1: ftile[256][65] | W1copy[4096] | Wseg[1280] | bseg[20] | cw[20]
#define P1_FTILE 0
#define P1_W1    16640
#define P1_WSEG  20736
#define P1_BSEG  22016
#define P1_CW    22036
#define SM1_BYTES (22056 * 4)
// pass3: htile[256][65] | AB[64]f2 | W2p[64]f4
#define SM3_BYTES (17024 * 4)

// ---------------- init ---------------------------------------------------------
__global__ void zero_kernel() {
    int t = threadIdx.x;
    if (t < 5) g_acc[t] = 0.0;
    if (t < CC) { g_sum[t] = 0.0; g_sumsq[t] = 0.0; }
}

// ---------------- pass 1: h0 = feat@W1 (stored), BN stats, seg CE loss --------
__global__ __launch_bounds__(256, 2) void pass1_kernel(
    const float* __restrict__ feat, const int* __restrict__ segment,
    const float* __restrict__ W1, const float* __restrict__ Wseg,
    const float* __restrict__ bseg, const float* __restrict__ cw,
    int N, int ntiles)
{
    extern __shared__ float sm[];
    float* ftile = sm + P1_FTILE;
    float* w1f   = sm + P1_W1;
    float* wsf   = sm + P1_WSEG;
    float* bsf   = sm + P1_BSEG;
    float* cwf   = sm + P1_CW;
    const int tid = threadIdx.x;

    for (int i = tid; i < CC * CC; i += 256) w1f[i] = W1[i];
    for (int i = tid; i < CC * KK; i += 256) wsf[i] = Wseg[i];
    if (tid < KK) { bsf[tid] = bseg[tid]; cwf[tid] = cw[tid]; }
    __syncthreads();

    const ulonglong2* w12 = (const ulonglong2*)w1f;   // 16 x ull2 per k-row
    const ulonglong2* ws2 = (const ulonglong2*)wsf;   // 5  x ull2 per k-row
    const ull* bs2 = (const ull*)bsf;

    float segnum = 0.f, segden = 0.f, ssum = 0.f, ssq = 0.f;
    const int cch = tid & 63, q = tid >> 6;
    const int NE = N * CC;

    for (int t = blockIdx.x; t < ntiles; t += gridDim.x) {
        const int base = t * TILE;
        // coalesced, padded tile load (zero-fill tail)
#pragma unroll 4
        for (int r = 0; r < 64; r++) {
            int l = r * 256 + tid;
            int gi = base * CC + l;
            ftile[(l >> 6) * 65 + (l & 63)] = (gi < NE) ? feat[gi] : 0.f;
        }
        __syncthreads();

        const int p = base + tid;
        const bool inr = (p < N);
        const float* frow = ftile + tid * 65;

        // ---- phase B: seg logits + CE (low reg pressure) ----
        ull lg[10];
#pragma unroll
        for (int j = 0; j < 10; j++) lg[j] = bs2[j];
#pragma unroll 4
        for (int k = 0; k < CC; k++) {
            ull fk2 = bcast2(frow[k]);
#pragma unroll
            for (int j = 0; j < 5; j++) {
                ulonglong2 w = ws2[k * 5 + j];
                lg[2 * j]     = fma2(fk2, w.x, lg[2 * j]);
                lg[2 * j + 1] = fma2(fk2, w.y, lg[2 * j + 1]);
            }
        }
        float l[KK];
#pragma unroll
        for (int j = 0; j < 10; j++) { float2 v = unpk(lg[j]); l[2 * j] = v.x; l[2 * j + 1] = v.y; }
        float m = l[0];
#pragma unroll
        for (int k = 1; k < KK; k++) m = fmaxf(m, l[k]);
        float s = 0.f;
#pragma unroll
        for (int k = 0; k < KK; k++) s += __expf(l[k] - m);
        float lse = m + __logf(s);
        int sg = inr ? segment[p] : -1;
        bool valid = inr && (sg != -1);
        int tgt = valid ? sg : 0;
        float lt = l[0];
#pragma unroll
        for (int k = 1; k < KK; k++) lt = (k == tgt) ? l[k] : lt;
        float w = valid ? cwf[tgt] : 0.f;
        segnum += w * (lse - lt);
        segden += w;

        // ---- phase A: h0 = f @ W1 (32 packed accumulators) ----
        ull acc[32];
#pragma unroll
        for (int j = 0; j < 32; j++) acc[j] = 0ull;
#pragma unroll 2
        for (int k = 0; k < CC; k++) {
            ull fk2 = bcast2(frow[k]);
#pragma unroll
            for (int j = 0; j < 16; j++) {
                ulonglong2 ww = w12[k * 16 + j];
                acc[2 * j]     = fma2(fk2, ww.x, acc[2 * j]);
                acc[2 * j + 1] = fma2(fk2, ww.y, acc[2 * j + 1]);
            }
        }
        __syncthreads();   // everyone done reading ftile

        // write h0 back into tile (conflict-free), then stats + coalesced store
        float* orow = ftile + tid * 65;
#pragma unroll
        for (int j = 0; j < 32; j++) {
            float2 v = unpk(acc[j]);
            orow[2 * j] = v.x; orow[2 * j + 1] = v.y;
        }
        __syncthreads();
#pragma unroll 4
        for (int r = 0; r < 64; r++) {
            float v = ftile[(q * 64 + r) * 65 + cch];
            ssum += v;
            ssq = fmaf(v, v, ssq);
        }
#pragma unroll 4
        for (int r = 0; r < 64; r++) {
            int lidx = r * 256 + tid;
            int gi = base * CC + lidx;
            if (gi < NE) g_h0[gi] = ftile[(lidx >> 6) * 65 + (lidx & 63)];
        }
        __syncthreads();
    }

    // ---- block reductions -> double atomics ----
    float sn = wsum(segnum), sd = wsum(segden);
    const int wid = tid >> 5, lid = tid & 31;
    if (lid == 0) { ftile[wid] = sn; ftile[8 + wid] = sd; }
    __syncthreads();
    if (tid == 0) {
        float a = 0, b = 0;
        for (int i = 0; i < 8; i++) { a += ftile[i]; b += ftile[8 + i]; }
        atomicAdd(&g_acc[0], (double)a);
        atomicAdd(&g_acc[1], (double)b);
    }
    __syncthreads();
    ftile[tid] = ssum; ftile[256 + tid] = ssq;
    __syncthreads();
    if (tid < CC) {
        float a = ftile[tid] + ftile[tid + 64] + ftile[tid + 128] + ftile[tid + 192];
        float b = ftile[256 + tid] + ftile[256 + tid + 64] + ftile[256 + tid + 128] + ftile[256 + tid + 192];
        atomicAdd(&g_sum[tid], (double)a);
        atomicAdd(&g_sumsq[tid], (double)b);
    }
}

// ---------------- finalize BN affine (b1 cancels through BN) ------------------
__global__ void finalize_kernel(const float* __restrict__ gamma,
                                const float* __restrict__ beta,
                                const float* __restrict__ W2, int N)
{
    int c = threadIdx.x;
    if (c < CC) {
        double inv_n = 1.0 / (double)N;
        double m0  = g_sum[c] * inv_n;
        double var = g_sumsq[c] * inv_n - m0 * m0;
        float inv = rsqrtf((float)var + 1e-3f);
        float A = gamma[c] * inv;
        float B = beta[c] - (float)m0 * A;
        g_AB[c]  = make_float2(A, B);
        g_W2p[c] = make_float4(W2[3 * c], W2[3 * c + 1], W2[3 * c + 2], 0.f);
    }
}

// ---------------- pass 3: bias head + L1 + cosine losses ----------------------
__global__ __launch_bounds__(256, 2) void pass3_kernel(
    const float* __restrict__ coord, const int* __restrict__ instance,
    const float* __restrict__ cent, const float* __restrict__ b2,
    int N, int ntiles)
{
    extern __shared__ float sm[];
    float* htile = sm;
    float2* ABs = (float2*)(sm + 16640);
    float4* W2s = (float4*)(sm + 16768);
    const int tid = threadIdx.x;
    if (tid < CC) { ABs[tid] = g_AB[tid]; W2s[tid] = g_W2p[tid]; }
    __syncthreads();
    const float b20 = b2[0], b21 = b2[1], b22 = b2[2];
    const int NE = N * CC;

    float aL1 = 0.f, aCos = 0.f, aCnt = 0.f;
    for (int t = blockIdx.x; t < ntiles; t += gridDim.x) {
        const int base = t * TILE;
#pragma unroll 4
        for (int r = 0; r < 64; r++) {
            int lidx = r * 256 + tid;
            int gi = base * CC + lidx;
            htile[(lidx >> 6) * 65 + (lidx & 63)] = (gi < NE) ? g_h0[gi] : 0.f;
        }
        __syncthreads();
        const int p = base + tid;
        float p0 = b20, p1 = b21, p2 = b22;
        const float* hrow = htile + tid * 65;
#pragma unroll 4
        for (int k = 0; k < CC; k++) {
            float h = hrow[k];
            float2 ab = ABs[k];
            float v = fmaf(h, ab.x, ab.y);
            float r = fmaxf(v, 0.f);
            float4 ww = W2s[k];
            p0 = fmaf(r, ww.x, p0);
            p1 = fmaf(r, ww.y, p1);
            p2 = fmaf(r, ww.z, p2);
        }
        if (p < N && instance[p] != -1) {
            float g0 = cent[3 * p]     - coord[3 * p];
            float g1 = cent[3 * p + 1] - coord[3 * p + 1];
            float g2 = cent[3 * p + 2] - coord[3 * p + 2];
            aL1 += fabsf(p0 - g0) + fabsf(p1 - g1) + fabsf(p2 - g2);
            float np = sqrtf(p0 * p0 + p1 * p1 + p2 * p2);
            float ng = sqrtf(g0 * g0 + g1 * g1 + g2 * g2);
            float dt = p0 * g0 + p1 * g1 + p2 * g2;
            aCos += -dt / ((np + 1e-8f) * (ng + 1e-8f));
            aCnt += 1.f;
        }
        __syncthreads();
    }
    float a = wsum(aL1), b = wsum(aCos), c = wsum(aCnt);
    int wid = tid >> 5, lid = tid & 31;
    if (lid == 0) { htile[wid] = a; htile[8 + wid] = b; htile[16 + wid] = c; }
    __syncthreads();
    if (tid == 0) {
        float x = 0, y = 0, z = 0;
        for (int i = 0; i < 8; i++) { x += htile[i]; y += htile[8 + i]; z += htile[16 + i]; }
        atomicAdd(&g_acc[2], (double)x);
        atomicAdd(&g_acc[3], (double)y);
        atomicAdd(&g_acc[4], (double)z);
    }
}

// ---------------- final combine ------------------------------------------------
__global__ void out_kernel(float* __restrict__ out) {
    double seg   = g_acc[0] / g_acc[1];
    double denom = g_acc[4] + 1e-8;
    double l1    = g_acc[2] / denom;
    double cs    = g_acc[3] / denom;
    out[0] = (float)(seg + l1 + cs);
    out[1] = (float)seg;
    out[2] = (float)l1;
    out[3] = (float)cs;
}

// ---------------- launch --------------------------------------------------------
extern "C" void kernel_launch(void* const* d_in, const int* in_sizes, int n_in,
                              void* d_out, int out_size)
{
    const float* feat     = (const float*)d_in[0];
    const float* coord    = (const float*)d_in[1];
    const int*   segment  = (const int*)d_in[2];
    const int*   instance = (const int*)d_in[3];
    const float* cent     = (const float*)d_in[4];
    const float* W1       = (const float*)d_in[5];
    // d_in[6] = b1 (cancels through BN)
    const float* gamma    = (const float*)d_in[7];
    const float* beta     = (const float*)d_in[8];
    const float* W2       = (const float*)d_in[9];
    const float* b2       = (const float*)d_in[10];
    const float* Wseg     = (const float*)d_in[11];
    const float* bseg     = (const float*)d_in[12];
    const float* cw       = (const float*)d_in[13];

    int N = in_sizes[0] / CC;
    if (N > NMAX) N = NMAX;  // scratch capacity (dataset is N = 1<<20)
    int ntiles = (N + TILE - 1) / TILE;
    int grid = ntiles < 296 ? ntiles : 296;

    cudaFuncSetAttribute(pass1_kernel, cudaFuncAttributeMaxDynamicSharedMemorySize, SM1_BYTES);
    cudaFuncSetAttribute(pass3_kernel, cudaFuncAttributeMaxDynamicSharedMemorySize, SM3_BYTES);

    zero_kernel<<<1, 64>>>();
    pass1_kernel<<<grid, 256, SM1_BYTES>>>(feat, segment, W1, Wseg, bseg, cw, N, ntiles);
    finalize_kernel<<<1, 64>>>(gamma, beta, W2, N);
    pass3_kernel<<<grid, 256, SM3_BYTES>>>(coord, instance, cent, b2, N, ntiles);
    out_kernel<<<1, 1>>>((float*)d_out);
}

// round 3
// speedup vs baseline: 1.6688x; 1.6688x over previous
#include <cuda_runtime.h>
#include <cuda_bf16.h>

#define CC 64
#define KK 20
#define TILE 256
#define NMAX (1 << 20)
#define MAXTILES (NMAX / TILE)

typedef unsigned long long ull;

// ---------------- device scratch (static; no allocations allowed) -------------
__device__ uint4  g_h0q[(size_t)MAXTILES * 2048];  // 128 MiB: h0 as bf16x2, tile-blocked
__device__ double g_acc[5];                        // segnum, segden, l1, cos, cnt
__device__ double g_sum[CC];
__device__ double g_sumsq[CC];
__device__ float2 g_AB[CC];                        // BN-folded affine: h0*A + B
__device__ float4 g_W2p[CC];                       // W2 rows padded to float4

// ---------------- f32x2 packed math (Blackwell) --------------------------------
__device__ __forceinline__ ull fma2(ull a, ull b, ull c) {
    ull d;
    asm("fma.rn.f32x2 %0, %1, %2, %3;" : "=l"(d) : "l"(a), "l"(b), "l"(c));
    return d;
}
__device__ __forceinline__ ull add2(ull a, ull b) {
    ull d;
    asm("add.rn.f32x2 %0, %1, %2;" : "=l"(d) : "l"(a), "l"(b));
    return d;
}
__device__ __forceinline__ ull bcast2(float x) {
    ull r;
    asm("mov.b64 %0, {%1, %1};" : "=l"(r) : "f"(x));
    return r;
}
__device__ __forceinline__ float2 unpk(ull v) {
    float lo, hi;
    asm("mov.b64 {%0, %1}, %2;" : "=f"(lo), "=f"(hi) : "l"(v));
    return make_float2(lo, hi);
}
// pack f32x2 -> bf16x2; low half of result = low float of the pair
__device__ __forceinline__ unsigned cvt_bf16x2(ull packed_f32x2) {
    float2 v = unpk(packed_f32x2);
    unsigned r;
    asm("cvt.rn.bf16x2.f32 %0, %1, %2;" : "=r"(r) : "f"(v.y), "f"(v.x));
    return r;
}
__device__ __forceinline__ float wsum(float v) {
#pragma unroll
    for (int o = 16; o > 0; o >>= 1) v += __shfl_down_sync(0xffffffffu, v, o);
    return v;
}

// ---------------- pass1 smem layout (floats) -----------------------------------
// ft[64][257] | W1[4096] | Wseg[1280] | bseg[20] | cw[20]
#define FT_PAD 257
#define P1_W1   16448
#define P1_WSEG 20544
#define P1_BSEG 21824
#define P1_CW   21844
#define SM1_FLOATS 21872
#define SM1_BYTES (SM1_FLOATS * 4)

// ---------------- init ----------------------------------------------------------
__global__ void zero_kernel() {
    int t = threadIdx.x;
    if (t < 5) g_acc[t] = 0.0;
    if (t < CC) { g_sum[t] = 0.0; g_sumsq[t] = 0.0; }
}

// ---------------- pass 1: h0 = feat@W1 (bf16 store), BN stats, seg CE ----------
__global__ __launch_bounds__(256, 2) void pass1_kernel(
    const float* __restrict__ feat, const int* __restrict__ segment,
    const float* __restrict__ W1, const float* __restrict__ Wseg,
    const float* __restrict__ bseg, const float* __restrict__ cw,
    int N, int ntiles)
{
    extern __shared__ float sm[];
    float* ft  = sm;
    float* w1f = sm + P1_W1;
    float* wsf = sm + P1_WSEG;
    float* bsf = sm + P1_BSEG;
    float* cwf = sm + P1_CW;
    const int tid = threadIdx.x;
    const int c = tid & 63, r = tid >> 6;

    for (int i = tid; i < CC * CC; i += 256) w1f[i] = W1[i];
    for (int i = tid; i < CC * KK; i += 256) wsf[i] = Wseg[i];
    if (tid < KK) { bsf[tid] = bseg[tid]; cwf[tid] = cw[tid]; }
    __syncthreads();

    const ulonglong2* w1q = (const ulonglong2*)w1f;
    const ulonglong2* ws2 = (const ulonglong2*)wsf;
    const ull* bsu = (const ull*)bsf;

    float segnum = 0.f, segden = 0.f;
    ull ssum2[8], ssq2[8];
#pragma unroll
    for (int u = 0; u < 8; u++) { ssum2[u] = 0ull; ssq2[u] = 0ull; }

    for (int t = blockIdx.x; t < ntiles; t += gridDim.x) {
        const int base = t * TILE;

        // ---- load tile, transposed to channel-major ft[ch][pt] ----
        if (base + TILE <= N) {
            const float4* src = (const float4*)(feat + (size_t)base * CC);
#pragma unroll
            for (int it = 0; it < 16; it++) {
                float4 v = src[it * 256 + tid];
                int l4 = it * 256 + tid;
                int pt = l4 >> 4;
                int ch = (l4 & 15) * 4;
                ft[(ch + 0) * FT_PAD + pt] = v.x;
                ft[(ch + 1) * FT_PAD + pt] = v.y;
                ft[(ch + 2) * FT_PAD + pt] = v.z;
                ft[(ch + 3) * FT_PAD + pt] = v.w;
            }
        } else {
            for (int l = tid; l < TILE * CC; l += 256) {
                int pt = l >> 6, ch = l & 63;
                int g = base + pt;
                ft[ch * FT_PAD + pt] = (g < N) ? feat[(size_t)g * CC + ch] : 0.f;
            }
        }
        __syncthreads();

        // ---- seg logits + CE (thread = point tid) ----
        {
            ull lg[10];
#pragma unroll
            for (int j = 0; j < 10; j++) lg[j] = bsu[j];
#pragma unroll 4
            for (int k = 0; k < CC; k++) {
                ull f2 = bcast2(ft[k * FT_PAD + tid]);
#pragma unroll
                for (int j = 0; j < 5; j++) {
                    ulonglong2 w = ws2[k * 5 + j];
                    lg[2 * j]     = fma2(f2, w.x, lg[2 * j]);
                    lg[2 * j + 1] = fma2(f2, w.y, lg[2 * j + 1]);
                }
            }
            float l[KK];
#pragma unroll
            for (int j = 0; j < 10; j++) { float2 v = unpk(lg[j]); l[2 * j] = v.x; l[2 * j + 1] = v.y; }
            float m = l[0];
#pragma unroll
            for (int k = 1; k < KK; k++) m = fmaxf(m, l[k]);
            float s = 0.f;
#pragma unroll
            for (int k = 0; k < KK; k++) s += __expf(l[k] - m);
            float lse = m + __logf(s);
            int p = base + tid;
            bool inr = (p < N);
            int sg = inr ? segment[p] : -1;
            bool valid = inr && (sg != -1);
            int tgt = valid ? sg : 0;
            float lt = l[0];
#pragma unroll
            for (int k = 1; k < KK; k++) lt = (k == tgt) ? l[k] : lt;
            float w = valid ? cwf[tgt] : 0.f;
            segnum += w * (lse - lt);
            segden += w;
        }

        // ---- GEMM: thread computes points {c,c+64,c+128,c+192} x channels [16r,16r+16) ----
        ull acc[32];
#pragma unroll
        for (int j = 0; j < 32; j++) acc[j] = 0ull;
#pragma unroll 4
        for (int k = 0; k < CC; k++) {
            const float* fk = ft + k * FT_PAD + c;
            ull f0 = bcast2(fk[0]);
            ull f1 = bcast2(fk[64]);
            ull f2v = bcast2(fk[128]);
            ull f3 = bcast2(fk[192]);
            const ulonglong2* wr = w1q + k * 16 + r * 4;
#pragma unroll
            for (int tq = 0; tq < 4; tq++) {
                ulonglong2 w = wr[tq];
                acc[2 * tq]          = fma2(f0, w.x, acc[2 * tq]);
                acc[2 * tq + 1]      = fma2(f0, w.y, acc[2 * tq + 1]);
                acc[8 + 2 * tq]      = fma2(f1, w.x, acc[8 + 2 * tq]);
                acc[8 + 2 * tq + 1]  = fma2(f1, w.y, acc[8 + 2 * tq + 1]);
                acc[16 + 2 * tq]     = fma2(f2v, w.x, acc[16 + 2 * tq]);
                acc[16 + 2 * tq + 1] = fma2(f2v, w.y, acc[16 + 2 * tq + 1]);
                acc[24 + 2 * tq]     = fma2(f3, w.x, acc[24 + 2 * tq]);
                acc[24 + 2 * tq + 1] = fma2(f3, w.y, acc[24 + 2 * tq + 1]);
            }
        }

        // ---- BN stats accumulate (packed) ----
#pragma unroll
        for (int i = 0; i < 4; i++)
#pragma unroll
            for (int u = 0; u < 8; u++) {
                ull h = acc[i * 8 + u];
                ssum2[u] = add2(ssum2[u], h);
                ssq2[u]  = fma2(h, h, ssq2[u]);
            }

        // ---- store h0 as bf16x2, tile-blocked coalesced layout ----
        {
            uint4* dst = g_h0q + (size_t)t * 2048 + tid;
#pragma unroll
            for (int i = 0; i < 4; i++) {
#pragma unroll
                for (int q = 0; q < 2; q++) {
                    uint4 v;
                    v.x = cvt_bf16x2(acc[i * 8 + 4 * q + 0]);
                    v.y = cvt_bf16x2(acc[i * 8 + 4 * q + 1]);
                    v.z = cvt_bf16x2(acc[i * 8 + 4 * q + 2]);
                    v.w = cvt_bf16x2(acc[i * 8 + 4 * q + 3]);
                    dst[(i * 2 + q) * 256] = v;
                }
            }
        }
        __syncthreads();
    }

    // ---- block reductions -> double atomics ----
    float sn = wsum(segnum), sd = wsum(segden);
    const int wid = tid >> 5, lid = tid & 31;
    __syncthreads();
    if (lid == 0) { ft[wid] = sn; ft[8 + wid] = sd; }

    // stats: warp shuffle-reduce (all lanes in a warp share r -> same channels)
#pragma unroll
    for (int u = 0; u < 8; u++) {
#pragma unroll
        for (int o = 16; o > 0; o >>= 1) {
            ssum2[u] = add2(ssum2[u], __shfl_down_sync(0xffffffffu, ssum2[u], o));
            ssq2[u]  = add2(ssq2[u],  __shfl_down_sync(0xffffffffu, ssq2[u],  o));
        }
    }
    ull* sred = (ull*)(ft + 32);   // 128B-aligned, 128 ull
    if (lid == 0) {
#pragma unroll
        for (int u = 0; u < 8; u++) {
            sred[wid * 16 + u]     = ssum2[u];
            sred[wid * 16 + 8 + u] = ssq2[u];
        }
    }
    __syncthreads();
    if (tid == 0) {
        float a = 0, b = 0;
        for (int i = 0; i < 8; i++) { a += ft[i]; b += ft[8 + i]; }
        atomicAdd(&g_acc[0], (double)a);
        atomicAdd(&g_acc[1], (double)b);
    }
    if (tid < 64) {
        int q = tid >> 5, z = tid & 31;
        int r2 = z >> 3, u = z & 7;
        ull a = sred[(2 * r2) * 16 + q * 8 + u];
        ull b = sred[(2 * r2 + 1) * 16 + q * 8 + u];
        float2 v = unpk(add2(a, b));
        int ch = 16 * r2 + 2 * u;
        if (q == 0) {
            atomicAdd(&g_sum[ch],     (double)v.x);
            atomicAdd(&g_sum[ch + 1], (double)v.y);
        } else {
            atomicAdd(&g_sumsq[ch],     (double)v.x);
            atomicAdd(&g_sumsq[ch + 1], (double)v.y);
        }
    }
}

// ---------------- finalize BN affine (b1 cancels through BN) -------------------
__global__ void finalize_kernel(const float* __restrict__ gamma,
                                const float* __restrict__ beta,
                                const float* __restrict__ W2, int N)
{
    int ch = threadIdx.x;
    if (ch < CC) {
        double inv_n = 1.0 / (double)N;
        double m0  = g_sum[ch] * inv_n;
        double var = g_sumsq[ch] * inv_n - m0 * m0;
        float inv = rsqrtf((float)var + 1e-3f);
        float A = gamma[ch] * inv;
        float B = beta[ch] - (float)m0 * A;
        g_AB[ch]  = make_float2(A, B);
        g_W2p[ch] = make_float4(W2[3 * ch], W2[3 * ch + 1], W2[3 * ch + 2], 0.f);
    }
}

// ---------------- pass 3: bias head + L1 + cosine losses -----------------------
__global__ __launch_bounds__(256) void pass3_kernel(
    const float* __restrict__ coord, const int* __restrict__ instance,
    const float* __restrict__ cent, const float* __restrict__ b2,
    int N, int ntiles)
{
    __shared__ float2 ABs[CC];
    __shared__ float4 W2s[CC];
    __shared__ float  sred3[4 * 256 * 3];
    __shared__ float  rbuf[24];

    const int tid = threadIdx.x;
    const int c = tid & 63, r = tid >> 6;
    if (tid < CC) { ABs[tid] = g_AB[tid]; W2s[tid] = g_W2p[tid]; }
    const float b20 = b2[0], b21 = b2[1], b22 = b2[2];
    __syncthreads();

    float aL1 = 0.f, aCos = 0.f, aCnt = 0.f;

    for (int t = blockIdx.x; t < ntiles; t += gridDim.x) {
        const int base = t * TILE;
        const uint4* src = g_h0q + (size_t)t * 2048 + tid;
        uint4 hq[8];
#pragma unroll
        for (int q8 = 0; q8 < 8; q8++) hq[q8] = src[q8 * 256];

        float pr[4][3];
#pragma unroll
        for (int i = 0; i < 4; i++) { pr[i][0] = 0.f; pr[i][1] = 0.f; pr[i][2] = 0.f; }

#pragma unroll
        for (int i = 0; i < 4; i++) {
#pragma unroll
            for (int q = 0; q < 2; q++) {
                uint4 v = hq[i * 2 + q];
                unsigned comps[4] = {v.x, v.y, v.z, v.w};
#pragma unroll
                for (int cm = 0; cm < 4; cm++) {
                    int ch0 = 16 * r + 8 * q + 2 * cm;
                    __nv_bfloat162 bb = *reinterpret_cast<__nv_bfloat162*>(&comps[cm]);
                    float2 hh = __bfloat1622float2(bb);
                    float2 ab0 = ABs[ch0], ab1 = ABs[ch0 + 1];
                    float v0 = fmaxf(fmaf(hh.x, ab0.x, ab0.y), 0.f);
                    float v1 = fmaxf(fmaf(hh.y, ab1.x, ab1.y), 0.f);
                    float4 w0 = W2s[ch0], w1 = W2s[ch0 + 1];
                    pr[i][0] = fmaf(v0, w0.x, fmaf(v1, w1.x, pr[i][0]));
                    pr[i][1] = fmaf(v0, w0.y, fmaf(v1, w1.y, pr[i][1]));
                    pr[i][2] = fmaf(v0, w0.z, fmaf(v1, w1.z, pr[i][2]));
                }
            }
        }
#pragma unroll
        for (int i = 0; i < 4; i++) {
            int pt = c + 64 * i;
            sred3[(r * 256 + pt) * 3 + 0] = pr[i][0];
            sred3[(r * 256 + pt) * 3 + 1] = pr[i][1];
            sred3[(r * 256 + pt) * 3 + 2] = pr[i][2];
        }
        __syncthreads();
        if (r == 0) {
#pragma unroll
            for (int i = 0; i < 4; i++) {
                int pt = c + 64 * i;
                int g = base + pt;
                if (g < N) {
                    int inst = instance[g];
                    if (inst != -1) {
                        float p0 = b20, p1 = b21, p2 = b22;
#pragma unroll
                        for (int rr = 0; rr < 4; rr++) {
                            p0 += sred3[(rr * 256 + pt) * 3 + 0];
                            p1 += sred3[(rr * 256 + pt) * 3 + 1];
                            p2 += sred3[(rr * 256 + pt) * 3 + 2];
                        }
                        float g0 = cent[3 * g]     - coord[3 * g];
                        float g1 = cent[3 * g + 1] - coord[3 * g + 1];
                        float g2 = cent[3 * g + 2] - coord[3 * g + 2];
                        aL1 += fabsf(p0 - g0) + fabsf(p1 - g1) + fabsf(p2 - g2);
                        float np = sqrtf(p0 * p0 + p1 * p1 + p2 * p2);
                        float ng = sqrtf(g0 * g0 + g1 * g1 + g2 * g2);
                        float dt = p0 * g0 + p1 * g1 + p2 * g2;
                        aCos += -dt / ((np + 1e-8f) * (ng + 1e-8f));
                        aCnt += 1.f;
                    }
                }
            }
        }
        __syncthreads();
    }

    float a = wsum(aL1), b = wsum(aCos), cc2 = wsum(aCnt);
    int wid = tid >> 5, lid = tid & 31;
    if (lid == 0) { rbuf[wid] = a; rbuf[8 + wid] = b; rbuf[16 + wid] = cc2; }
    __syncthreads();
    if (tid == 0) {
        float x = 0, y = 0, z = 0;
        for (int i = 0; i < 8; i++) { x += rbuf[i]; y += rbuf[8 + i]; z += rbuf[16 + i]; }
        atomicAdd(&g_acc[2], (double)x);
        atomicAdd(&g_acc[3], (double)y);
        atomicAdd(&g_acc[4], (double)z);
    }
}

// ---------------- final combine -------------------------------------------------
__global__ void out_kernel(float* __restrict__ out) {
    double seg   = g_acc[0] / g_acc[1];
    double denom = g_acc[4] + 1e-8;
    double l1    = g_acc[2] / denom;
    double cs    = g_acc[3] / denom;
    out[0] = (float)(seg + l1 + cs);
    out[1] = (float)seg;
    out[2] = (float)l1;
    out[3] = (float)cs;
}

// ---------------- launch ---------------------------------------------------------
extern "C" void kernel_launch(void* const* d_in, const int* in_sizes, int n_in,
                              void* d_out, int out_size)
{
    const float* feat     = (const float*)d_in[0];
    const float* coord    = (const float*)d_in[1];
    const int*   segment  = (const int*)d_in[2];
    const int*   instance = (const int*)d_in[3];
    const float* cent     = (const float*)d_in[4];
    const float* W1       = (const float*)d_in[5];
    // d_in[6] = b1 (cancels through BN)
    const float* gamma    = (const float*)d_in[7];
    const float* beta     = (const float*)d_in[8];
    const float* W2       = (const float*)d_in[9];
    const float* b2       = (const float*)d_in[10];
    const float* Wseg     = (const float*)d_in[11];
    const float* bseg     = (const float*)d_in[12];
    const float* cw       = (const float*)d_in[13];

    int N = in_sizes[0] / CC;
    if (N > NMAX) N = NMAX;  // scratch capacity (dataset is N = 1<<20)
    int ntiles = (N + TILE - 1) / TILE;
    int grid1 = ntiles < 296 ? ntiles : 296;
    int grid3 = ntiles < 592 ? ntiles : 592;

    cudaFuncSetAttribute(pass1_kernel, cudaFuncAttributeMaxDynamicSharedMemorySize, SM1_BYTES);

    zero_kernel<<<1, 64>>>();
    pass1_kernel<<<grid1, 256, SM1_BYTES>>>(feat, segment, W1, Wseg, bseg, cw, N, ntiles);
    finalize_kernel<<<1, 64>>>(gamma, beta, W2, N);
    pass3_kernel<<<grid3, 256>>>(coord, instance, cent, b2, N, ntiles);
    out_kernel<<<1, 1>>>((float*)d_out);
}

// round 6
// speedup vs baseline: 3.9921x; 2.3922x over previous
#include <cuda_runtime.h>
#include <cuda_bf16.h>
#include <cstdint>

#define CC 64
#define KK 20
#define MT 128             // points per pass1 tile
#define NMAX (1 << 20)

// ---------------- device scratch (static; no allocations allowed) -------------
__device__ uint4  g_h0q[(size_t)NMAX * 8];   // 128 MiB: h0 bf16, point-major rows of 128B
__device__ double g_acc[5];                  // segnum, segden, l1, cos, cnt
__device__ double g_sum[CC];
__device__ double g_sumsq[CC];
__device__ float2 g_AB[CC];                  // BN-folded affine: h0*A + B
__device__ float4 g_W2p[CC];

// ---------------- helpers -------------------------------------------------------
__device__ __forceinline__ uint32_t smem_u32(const void* p) {
    uint32_t a;
    asm("{ .reg .u64 t; cvta.to.shared.u64 t, %1; cvt.u32.u64 %0, t; }" : "=r"(a) : "l"(p));
    return a;
}
// pack (hi, lo) -> bf16x2 (low half = lo)
__device__ __forceinline__ unsigned bf2(float hi, float lo) {
    unsigned r;
    asm("cvt.rn.bf16x2.f32 %0, %1, %2;" : "=r"(r) : "f"(hi), "f"(lo));
    return r;
}
__device__ __forceinline__ float wsum(float v) {
#pragma unroll
    for (int o = 16; o > 0; o >>= 1) v += __shfl_down_sync(0xffffffffu, v, o);
    return v;
}
__device__ __forceinline__ void ldsm_x4(uint32_t& a0, uint32_t& a1, uint32_t& a2, uint32_t& a3, uint32_t addr) {
    asm volatile("ldmatrix.sync.aligned.m8n8.x4.shared.b16 {%0,%1,%2,%3}, [%4];"
        : "=r"(a0), "=r"(a1), "=r"(a2), "=r"(a3) : "r"(addr));
}
__device__ __forceinline__ void mma16816(float* d, uint32_t a0, uint32_t a1, uint32_t a2, uint32_t a3,
                                         uint32_t b0, uint32_t b1) {
    asm volatile("mma.sync.aligned.m16n8k16.row.col.f32.bf16.bf16.f32 "
        "{%0,%1,%2,%3}, {%4,%5,%6,%7}, {%8,%9}, {%0,%1,%2,%3};"
        : "+f"(d[0]), "+f"(d[1]), "+f"(d[2]), "+f"(d[3])
        : "r"(a0), "r"(a1), "r"(a2), "r"(a3), "r"(b0), "r"(b1));
}

// ---------------- pass1 smem byte offsets ---------------------------------------
// A: 128 rows x 144B | B: 88 rows x 144B | stg: 128x36 u32 | lstg: 128x26 f32 | bs/cw
#define SO_A    0
#define SO_B    18432
#define SO_STG  31104
#define SO_LST  49536
#define SO_BS   62848
#define SO_CW   62928
#define SM1_BYTES 63040

// ---------------- init ----------------------------------------------------------
__global__ void zero_kernel() {
    int t = threadIdx.x;
    if (t < 5) g_acc[t] = 0.0;
    if (t < CC) { g_sum[t] = 0.0; g_sumsq[t] = 0.0; }
}

// ---------------- pass1: HMMA GEMM + BN stats + CE + h0 store -------------------
__global__ __launch_bounds__(256, 2) void pass1_kernel(
    const float* __restrict__ feat, const int* __restrict__ segment,
    const float* __restrict__ W1, const float* __restrict__ Wseg,
    const float* __restrict__ bseg, const float* __restrict__ cw,
    int N, int ntiles)
{
    extern __shared__ char sm[];
    const uint32_t smb = smem_u32(sm);
    unsigned* stg = (unsigned*)(sm + SO_STG);
    float* lstg = (float*)(sm + SO_LST);
    float* bsf = (float*)(sm + SO_BS);
    float* cwf = (float*)(sm + SO_CW);
    const int tid = threadIdx.x;
    const int w = tid >> 5, lane = tid & 31;
    const int gid = lane >> 2, tig = lane & 3;

    // B = [W1 | Wseg | 0]: rows n (out ch), cols k; bf16, pitch 144B
    for (int i = tid; i < 88 * CC; i += 256) {
        int n = i >> 6, k = i & 63;
        float v = (n < 64) ? W1[k * 64 + n] : ((n < 84) ? Wseg[k * 20 + (n - 64)] : 0.f);
        *(__nv_bfloat16*)(sm + SO_B + n * 144 + 2 * k) = __float2bfloat16(v);
    }
    if (tid < KK) { bsf[tid] = bseg[tid]; cwf[tid] = cw[tid]; }
    __syncthreads();

    // per-thread fixed addresses
    const uint32_t aAddrBase = smb + SO_A + (16 * w + (lane & 15)) * 144 + 16 * (lane >> 4);
    const uint32_t bAddrBase = smb + SO_B + gid * 144 + tig * 4;

    float segnum = 0.f, segden = 0.f;
    float s0 = 0.f, s1 = 0.f, q0 = 0.f, q1 = 0.f;

    for (int t = blockIdx.x; t < ntiles; t += gridDim.x) {
        const int base = t * MT;

        // ---- A tile: feat[128 x 64] f32 -> bf16 smem (pitch 144B) ----
        if (base + MT <= N) {
            const float4* src = (const float4*)(feat + (size_t)base * CC);
#pragma unroll
            for (int it = 0; it < 8; it++) {
                int l4 = it * 256 + tid;
                float4 v = src[l4];
                int pt = l4 >> 4, c4 = (l4 & 15) * 4;
                *(uint2*)(sm + SO_A + pt * 144 + c4 * 2) =
                    make_uint2(bf2(v.y, v.x), bf2(v.w, v.z));
            }
        } else {
            for (int l = tid; l < MT * CC / 2; l += 256) {
                int pt = l >> 5, c2 = (l & 31) * 2;
                int g = base + pt;
                float x = (g < N) ? feat[(size_t)g * CC + c2] : 0.f;
                float y = (g < N) ? feat[(size_t)g * CC + c2 + 1] : 0.f;
                *(unsigned*)(sm + SO_A + pt * 144 + c2 * 2) = bf2(y, x);
            }
        }
        __syncthreads();

        // ---- GEMM: D[128 x 88] = A @ B^T via m16n8k16, warp owns 16 rows ----
        float acc[11][4];
#pragma unroll
        for (int j = 0; j < 11; j++) {
            acc[j][0] = 0.f; acc[j][1] = 0.f; acc[j][2] = 0.f; acc[j][3] = 0.f;
        }
#pragma unroll
        for (int s = 0; s < 4; s++) {
            uint32_t a0, a1, a2, a3;
            ldsm_x4(a0, a1, a2, a3, aAddrBase + 32 * s);
            uint32_t bA = bAddrBase + 32 * s;
#pragma unroll
            for (int j = 0; j < 11; j++) {
                uint32_t b0, b1;
                asm volatile("ld.shared.b32 %0, [%1];" : "=r"(b0) : "r"(bA + j * 1152));
                asm volatile("ld.shared.b32 %0, [%1];" : "=r"(b1) : "r"(bA + j * 1152 + 16));
                mma16816(acc[j], a0, a1, a2, a3, b0, b1);
            }
        }

        // ---- stage results: h (cols 0..63) as bf16x2, logits (64..83) f32 ----
        {
            int r0 = 16 * w + gid;
#pragma unroll
            for (int j = 0; j < 8; j++) {
                stg[r0 * 36 + 4 * j + tig]       = bf2(acc[j][1], acc[j][0]);
                stg[(r0 + 8) * 36 + 4 * j + tig] = bf2(acc[j][3], acc[j][2]);
            }
#pragma unroll
            for (int j = 8; j < 11; j++) {
                int cl = 8 * (j - 8) + 2 * tig;
                if (cl < 20) {
                    *(float2*)(lstg + r0 * 26 + cl)       = make_float2(acc[j][0], acc[j][1]);
                    *(float2*)(lstg + (r0 + 8) * 26 + cl) = make_float2(acc[j][2], acc[j][3]);
                }
            }
        }
        __syncthreads();

        // ---- CE (tid < 128, one point each) ----
        if (tid < 128) {
            float l[KK];
#pragma unroll
            for (int k = 0; k < KK; k++) l[k] = lstg[tid * 26 + k] + bsf[k];
            float m = l[0];
#pragma unroll
            for (int k = 1; k < KK; k++) m = fmaxf(m, l[k]);
            float s = 0.f;
#pragma unroll
            for (int k = 0; k < KK; k++) s += __expf(l[k] - m);
            float lse = m + __logf(s);
            int p = base + tid;
            bool inr = (p < N);
            int sg = inr ? segment[p] : -1;
            bool valid = inr && (sg != -1);
            int tg = valid ? sg : 0;
            float lt = l[0];
#pragma unroll
            for (int k = 1; k < KK; k++) lt = (k == tg) ? l[k] : lt;
            float wt = valid ? cwf[tg] : 0.f;
            segnum += wt * (lse - lt);
            segden += wt;
        }

        // ---- BN stats (channel-major scan of stage) ----
        {
            int j = lane, g8 = w;   // col pair j (0..31), 16 points per thread group
#pragma unroll
            for (int q = 0; q < 16; q++) {
                int pt = g8 * 16 + q;
                if (base + pt < N) {
                    unsigned u = stg[pt * 36 + j];
                    float2 hh = __bfloat1622float2(*(__nv_bfloat162*)&u);
                    s0 += hh.x; s1 += hh.y;
                    q0 = fmaf(hh.x, hh.x, q0);
                    q1 = fmaf(hh.y, hh.y, q1);
                }
            }
        }
        // ---- coalesced h0 store (point-major, 128B per point) ----
#pragma unroll
        for (int it = 0; it < 4; it++) {
            int idx = it * 256 + tid;
            int pt = idx >> 3, c8 = idx & 7;
            if (base + pt < N) {
                uint4 v = *(uint4*)(stg + pt * 36 + c8 * 4);
                g_h0q[(size_t)(base + pt) * 8 + c8] = v;
            }
        }
        __syncthreads();
    }

    // ---- reductions -> double atomics ----
    float sn = wsum(segnum), sd = wsum(segden);
    float* red = (float*)stg;
    if (lane == 0) { red[1024 + w] = sn; red[1040 + w] = sd; }
    red[tid] = s0; red[256 + tid] = s1; red[512 + tid] = q0; red[768 + tid] = q1;
    __syncthreads();
    if (tid == 0) {
        float a = 0.f, b = 0.f;
        for (int i = 0; i < 8; i++) { a += red[1024 + i]; b += red[1040 + i]; }
        atomicAdd(&g_acc[0], (double)a);
        atomicAdd(&g_acc[1], (double)b);
    }
    if (tid < 32) {
        float a0 = 0.f, a1 = 0.f, b0 = 0.f, b1 = 0.f;
        for (int g = 0; g < 8; g++) {
            a0 += red[g * 32 + tid];
            a1 += red[256 + g * 32 + tid];
            b0 += red[512 + g * 32 + tid];
            b1 += red[768 + g * 32 + tid];
        }
        atomicAdd(&g_sum[2 * tid],       (double)a0);
        atomicAdd(&g_sum[2 * tid + 1],   (double)a1);
        atomicAdd(&g_sumsq[2 * tid],     (double)b0);
        atomicAdd(&g_sumsq[2 * tid + 1], (double)b1);
    }
}

// ---------------- finalize BN affine (b1 cancels through BN) -------------------
__global__ void finalize_kernel(const float* __restrict__ gamma,
                                const float* __restrict__ beta,
                                const float* __restrict__ W2, int N)
{
    int ch = threadIdx.x;
    if (ch < CC) {
        double inv_n = 1.0 / (double)N;
        double m0  = g_sum[ch] * inv_n;
        double var = g_sumsq[ch] * inv_n - m0 * m0;
        float inv = rsqrtf((float)var + 1e-3f);
        float A = gamma[ch] * inv;
        float B = beta[ch] - (float)m0 * A;
        g_AB[ch]  = make_float2(A, B);
        g_W2p[ch] = make_float4(W2[3 * ch], W2[3 * ch + 1], W2[3 * ch + 2], 0.f);
    }
}

// ---------------- pass3: bias head + L1 + cosine losses ------------------------
__global__ __launch_bounds__(256, 4) void pass3_kernel(
    const float* __restrict__ coord, const int* __restrict__ instance,
    const float* __restrict__ cent, const float* __restrict__ b2,
    int N, int nt3)
{
    __shared__ unsigned stg[256 * 33];
    __shared__ float2 ABs[CC];
    __shared__ float4 W2s[CC];
    __shared__ float rb[24];
    const int tid = threadIdx.x;
    if (tid < CC) { ABs[tid] = g_AB[tid]; W2s[tid] = g_W2p[tid]; }
    const float b20 = b2[0], b21 = b2[1], b22 = b2[2];
    __syncthreads();

    float aL1 = 0.f, aCos = 0.f, aCnt = 0.f;

    for (int t = blockIdx.x; t < nt3; t += gridDim.x) {
        const int base = t * 256;
#pragma unroll
        for (int it = 0; it < 8; it++) {
            int idx = it * 256 + tid;
            int pt = idx >> 3, c8 = idx & 7;
            uint4 v = make_uint4(0, 0, 0, 0);
            if (base + pt < N) v = g_h0q[(size_t)(base + pt) * 8 + c8];
            stg[pt * 33 + c8 * 4 + 0] = v.x;
            stg[pt * 33 + c8 * 4 + 1] = v.y;
            stg[pt * 33 + c8 * 4 + 2] = v.z;
            stg[pt * 33 + c8 * 4 + 3] = v.w;
        }
        __syncthreads();
        const int p = base + tid;
        float p0 = b20, p1 = b21, p2 = b22;
#pragma unroll
        for (int j = 0; j < 32; j++) {
            unsigned u = stg[tid * 33 + j];
            float2 hh = __bfloat1622float2(*(__nv_bfloat162*)&u);
            float2 a0 = ABs[2 * j], a1 = ABs[2 * j + 1];
            float v0 = fmaxf(fmaf(hh.x, a0.x, a0.y), 0.f);
            float v1 = fmaxf(fmaf(hh.y, a1.x, a1.y), 0.f);
            float4 w0 = W2s[2 * j], w1 = W2s[2 * j + 1];
            p0 = fmaf(v0, w0.x, fmaf(v1, w1.x, p0));
            p1 = fmaf(v0, w0.y, fmaf(v1, w1.y, p1));
            p2 = fmaf(v0, w0.z, fmaf(v1, w1.z, p2));
        }
        if (p < N) {
            int inst = instance[p];
            if (inst != -1) {
                float g0 = cent[3 * p]     - coord[3 * p];
                float g1 = cent[3 * p + 1] - coord[3 * p + 1];
                float g2 = cent[3 * p + 2] - coord[3 * p + 2];
                aL1 += fabsf(p0 - g0) + fabsf(p1 - g1) + fabsf(p2 - g2);
                float np = sqrtf(p0 * p0 + p1 * p1 + p2 * p2);
                float ng = sqrtf(g0 * g0 + g1 * g1 + g2 * g2);
                float dt = p0 * g0 + p1 * g1 + p2 * g2;
                aCos += -dt / ((np + 1e-8f) * (ng + 1e-8f));
                aCnt += 1.f;
            }
        }
        __syncthreads();
    }

    float a = wsum(aL1), b = wsum(aCos), c = wsum(aCnt);
    int wid = tid >> 5, lid = tid & 31;
    if (lid == 0) { rb[wid] = a; rb[8 + wid] = b; rb[16 + wid] = c; }
    __syncthreads();
    if (tid == 0) {
        float x = 0.f, y = 0.f, z = 0.f;
        for (int i = 0; i < 8; i++) { x += rb[i]; y += rb[8 + i]; z += rb[16 + i]; }
        atomicAdd(&g_acc[2], (double)x);
        atomicAdd(&g_acc[3], (double)y);
        atomicAdd(&g_acc[4], (double)z);
    }
}

// ---------------- final combine -------------------------------------------------
__global__ void out_kernel(float* __restrict__ out) {
    double seg   = g_acc[0] / g_acc[1];
    double denom = g_acc[4] + 1e-8;
    double l1    = g_acc[2] / denom;
    double cs    = g_acc[3] / denom;
    out[0] = (float)(seg + l1 + cs);
    out[1] = (float)seg;
    out[2] = (float)l1;
    out[3] = (float)cs;
}

// ---------------- launch ---------------------------------------------------------
extern "C" void kernel_launch(void* const* d_in, const int* in_sizes, int n_in,
                              void* d_out, int out_size)
{
    const float* feat     = (const float*)d_in[0];
    const float* coord    = (const float*)d_in[1];
    const int*   segment  = (const int*)d_in[2];
    const int*   instance = (const int*)d_in[3];
    const float* cent     = (const float*)d_in[4];
    const float* W1       = (const float*)d_in[5];
    // d_in[6] = b1 (cancels through BN)
    const float* gamma    = (const float*)d_in[7];
    const float* beta     = (const float*)d_in[8];
    const float* W2       = (const float*)d_in[9];
    const float* b2       = (const float*)d_in[10];
    const float* Wseg     = (const float*)d_in[11];
    const float* bseg     = (const float*)d_in[12];
    const float* cw       = (const float*)d_in[13];

    int N = in_sizes[0] / CC;
    if (N > NMAX) N = NMAX;
    int ntiles = (N + MT - 1) / MT;
    int nt3    = (N + 255) / 256;
    int grid1 = ntiles < 296 ? ntiles : 296;
    int grid3 = nt3 < 592 ? nt3 : 592;

    cudaFuncSetAttribute(pass1_kernel, cudaFuncAttributeMaxDynamicSharedMemorySize, SM1_BYTES);

    zero_kernel<<<1, 64>>>();
    pass1_kernel<<<grid1, 256, SM1_BYTES>>>(feat, segment, W1, Wseg, bseg, cw, N, ntiles);
    finalize_kernel<<<1, 64>>>(gamma, beta, W2, N);
    pass3_kernel<<<grid3, 256>>>(coord, instance, cent, b2, N, nt3);
    out_kernel<<<1, 1>>>((float*)d_out);
}

// round 8
// speedup vs baseline: 4.2762x; 1.0712x over previous
#include <cuda_runtime.h>
#include <cuda_bf16.h>
#include <cuda_fp16.h>
#include <cstdint>

#define CC 64
#define KK 20
#define MT 128             // points per pass1 tile
#define NMAX (1 << 20)

// ---------------- device scratch (static; no allocations allowed) -------------
__device__ uint4  g_h0q[(size_t)NMAX * 4];   // 64 MiB: h0 e4m3 fp8, point-major 64B rows
__device__ double g_acc[5];                  // segnum, segden, l1, cos, cnt
__device__ double g_sum[CC];
__device__ double g_sumsq[CC];
__device__ float2 g_AB[CC];                  // BN-folded affine: h0*A + B
__device__ float4 g_W2p[CC];

// ---------------- helpers -------------------------------------------------------
__device__ __forceinline__ uint32_t smem_u32(const void* p) {
    uint32_t a;
    asm("{ .reg .u64 t; cvta.to.shared.u64 t, %1; cvt.u32.u64 %0, t; }" : "=r"(a) : "l"(p));
    return a;
}
// pack (hi, lo) -> bf16x2 (low half = lo)
__device__ __forceinline__ unsigned bf2(float hi, float lo) {
    unsigned r;
    asm("cvt.rn.bf16x2.f32 %0, %1, %2;" : "=r"(r) : "f"(hi), "f"(lo));
    return r;
}
// pack (hi, lo) f32 -> e4m3x2 (16-bit)
__device__ __forceinline__ unsigned short fp8x2(float hi, float lo) {
    unsigned short r;
    asm("cvt.rn.satfinite.e4m3x2.f32 %0, %1, %2;" : "=h"(r) : "f"(hi), "f"(lo));
    return r;
}
// e4m3x2 (16-bit) -> half2
__device__ __forceinline__ __half2 fp8_to_h2(unsigned short v) {
    unsigned r;
    asm("cvt.rn.f16x2.e4m3x2 %0, %1;" : "=r"(r) : "h"(v));
    return *reinterpret_cast<__half2*>(&r);
}
__device__ __forceinline__ float wsum(float v) {
#pragma unroll
    for (int o = 16; o > 0; o >>= 1) v += __shfl_down_sync(0xffffffffu, v, o);
    return v;
}
__device__ __forceinline__ void ldsm_x4(uint32_t& a0, uint32_t& a1, uint32_t& a2, uint32_t& a3, uint32_t addr) {
    asm volatile("ldmatrix.sync.aligned.m8n8.x4.shared.b16 {%0,%1,%2,%3}, [%4];"
        : "=r"(a0), "=r"(a1), "=r"(a2), "=r"(a3) : "r"(addr));
}
__device__ __forceinline__ void mma16816(float* d, uint32_t a0, uint32_t a1, uint32_t a2, uint32_t a3,
                                         uint32_t b0, uint32_t b1) {
    asm volatile("mma.sync.aligned.m16n8k16.row.col.f32.bf16.bf16.f32 "
        "{%0,%1,%2,%3}, {%4,%5,%6,%7}, {%8,%9}, {%0,%1,%2,%3};"
        : "+f"(d[0]), "+f"(d[1]), "+f"(d[2]), "+f"(d[3])
        : "r"(a0), "r"(a1), "r"(a2), "r"(a3), "r"(b0), "r"(b1));
}

// ---------------- pass1 smem byte offsets ---------------------------------------
// A: 128 x 144B | B: 88 x 144B | stg: 128 x 36 u32 | bseg | cw
#define SO_A    0
#define SO_B    18432
#define SO_STG  31104
#define SO_BS   49536
#define SO_CW   49616
#define SM1_BYTES 49728

// ---------------- init ----------------------------------------------------------
__global__ void zero_kernel() {
    int t = threadIdx.x;
    if (t < 5) g_acc[t] = 0.0;
    if (t < CC) { g_sum[t] = 0.0; g_sumsq[t] = 0.0; }
}

// ---------------- pass1: HMMA GEMM + BN stats + CE + fp8 h0 store ---------------
__global__ __launch_bounds__(256, 3) void pass1_kernel(
    const float* __restrict__ feat, const int* __restrict__ segment,
    const float* __restrict__ W1, const float* __restrict__ Wseg,
    const float* __restrict__ bseg, const float* __restrict__ cw,
    int N, int ntiles)
{
    extern __shared__ char sm[];
    const uint32_t smb = smem_u32(sm);
    unsigned* stg = (unsigned*)(sm + SO_STG);
    float* bsf = (float*)(sm + SO_BS);
    float* cwf = (float*)(sm + SO_CW);
    const int tid = threadIdx.x;
    const int w = tid >> 5, lane = tid & 31;
    const int gid = lane >> 2, tig = lane & 3;

    // B = [W1 | Wseg | 0]: rows n (out ch), cols k; bf16, pitch 144B
    for (int i = tid; i < 88 * CC; i += 256) {
        int n = i >> 6, k = i & 63;
        float v = (n < 64) ? W1[k * 64 + n] : ((n < 84) ? Wseg[k * 20 + (n - 64)] : 0.f);
        *(__nv_bfloat16*)(sm + SO_B + n * 144 + 2 * k) = __float2bfloat16(v);
    }
    if (tid < KK) { bsf[tid] = bseg[tid]; cwf[tid] = cw[tid]; }
    __syncthreads();

    const uint32_t aAddrBase = smb + SO_A + (16 * w + (lane & 15)) * 144 + 16 * (lane >> 4);
    const uint32_t bAddrBase = smb + SO_B + gid * 144 + tig * 4;

    float segnum = 0.f, segden = 0.f;
    float s0 = 0.f, s1 = 0.f, q0 = 0.f, q1 = 0.f;

    for (int t = blockIdx.x; t < ntiles; t += gridDim.x) {
        const int base = t * MT;

        // ---- A tile: feat[128 x 64] f32 -> bf16 smem (pitch 144B) ----
        if (base + MT <= N) {
            const float4* src = (const float4*)(feat + (size_t)base * CC);
#pragma unroll
            for (int it = 0; it < 8; it++) {
                int l4 = it * 256 + tid;
                float4 v = src[l4];
                int pt = l4 >> 4, c4 = (l4 & 15) * 4;
                *(uint2*)(sm + SO_A + pt * 144 + c4 * 2) =
                    make_uint2(bf2(v.y, v.x), bf2(v.w, v.z));
            }
        } else {
            for (int l = tid; l < MT * CC / 2; l += 256) {
                int pt = l >> 5, c2 = (l & 31) * 2;
                int g = base + pt;
                float x = (g < N) ? feat[(size_t)g * CC + c2] : 0.f;
                float y = (g < N) ? feat[(size_t)g * CC + c2 + 1] : 0.f;
                *(unsigned*)(sm + SO_A + pt * 144 + c2 * 2) = bf2(y, x);
            }
        }
        __syncthreads();

        // ---- GEMM: D[128 x 88] = A @ B^T via m16n8k16, warp owns 16 rows ----
        float acc[11][4];
#pragma unroll
        for (int j = 0; j < 11; j++) {
            acc[j][0] = 0.f; acc[j][1] = 0.f; acc[j][2] = 0.f; acc[j][3] = 0.f;
        }
#pragma unroll
        for (int s = 0; s < 4; s++) {
            uint32_t a0, a1, a2, a3;
            ldsm_x4(a0, a1, a2, a3, aAddrBase + 32 * s);
            uint32_t bA = bAddrBase + 32 * s;
#pragma unroll
            for (int j = 0; j < 11; j++) {
                uint32_t b0, b1;
                asm volatile("ld.shared.b32 %0, [%1];" : "=r"(b0) : "r"(bA + j * 1152));
                asm volatile("ld.shared.b32 %0, [%1];" : "=r"(b1) : "r"(bA + j * 1152 + 16));
                mma16816(acc[j], a0, a1, a2, a3, b0, b1);
            }
        }

        // ---- CE directly from accumulators (quad shuffles), rows r0 and r0+8 ----
        {
            const int r0 = 16 * w + gid;
#pragma unroll
            for (int half = 0; half < 2; half++) {
                const int row = r0 + 8 * half;
                const int p = base + row;
                float m = -1e30f;
                float lv[6];
#pragma unroll
                for (int j = 0; j < 3; j++) {
#pragma unroll
                    for (int k = 0; k < 2; k++) {
                        int L = 8 * j + 2 * tig + k;
                        float v = (L < KK) ? (acc[8 + j][2 * half + k] + bsf[L]) : -1e30f;
                        lv[2 * j + k] = v;
                        m = fmaxf(m, v);
                    }
                }
                m = fmaxf(m, __shfl_xor_sync(0xffffffffu, m, 1));
                m = fmaxf(m, __shfl_xor_sync(0xffffffffu, m, 2));
                float s = 0.f;
#pragma unroll
                for (int i = 0; i < 6; i++) {
                    int L = 8 * (i >> 1) + 2 * tig + (i & 1);
                    if (L < KK) s += __expf(lv[i] - m);
                }
                s += __shfl_xor_sync(0xffffffffu, s, 1);
                s += __shfl_xor_sync(0xffffffffu, s, 2);
                float lse = m + __logf(s);
                bool inr = (p < N);
                int sg = inr ? segment[p] : -1;
                bool valid = inr && (sg != -1);
                int tgt = valid ? sg : 0;
                float lt = 0.f;
#pragma unroll
                for (int i = 0; i < 6; i++) {
                    int L = 8 * (i >> 1) + 2 * tig + (i & 1);
                    if (L < KK && L == tgt) lt += lv[i];
                }
                lt += __shfl_xor_sync(0xffffffffu, lt, 1);
                lt += __shfl_xor_sync(0xffffffffu, lt, 2);
                if (tig == 0) {
                    float wt = valid ? cwf[tgt] : 0.f;
                    segnum += wt * (lse - lt);
                    segden += wt;
                }
            }
        }

        // ---- stage h (cols 0..63) as bf16x2 ----
        {
            int r0 = 16 * w + gid;
#pragma unroll
            for (int j = 0; j < 8; j++) {
                stg[r0 * 36 + 4 * j + tig]       = bf2(acc[j][1], acc[j][0]);
                stg[(r0 + 8) * 36 + 4 * j + tig] = bf2(acc[j][3], acc[j][2]);
            }
        }
        __syncthreads();

        // ---- BN stats (channel-major scan of stage) ----
        {
            int j = lane, g8 = w;
#pragma unroll
            for (int q = 0; q < 16; q++) {
                int pt = g8 * 16 + q;
                if (base + pt < N) {
                    unsigned u = stg[pt * 36 + j];
                    float2 hh = __bfloat1622float2(*(__nv_bfloat162*)&u);
                    s0 += hh.x; s1 += hh.y;
                    q0 = fmaf(hh.x, hh.x, q0);
                    q1 = fmaf(hh.y, hh.y, q1);
                }
            }
        }
        // ---- fp8 h0 store (point-major, 64B per point) ----
#pragma unroll
        for (int it = 0; it < 2; it++) {
            int idx = it * 256 + tid;
            int pt = idx >> 2, c16 = idx & 3;
            if (base + pt < N) {
                unsigned r[4];
#pragma unroll
                for (int z = 0; z < 4; z++) {
                    unsigned u0 = stg[pt * 36 + c16 * 8 + 2 * z];
                    unsigned u1 = stg[pt * 36 + c16 * 8 + 2 * z + 1];
                    float2 f0 = __bfloat1622float2(*(__nv_bfloat162*)&u0);
                    float2 f1 = __bfloat1622float2(*(__nv_bfloat162*)&u1);
                    unsigned short e0 = fp8x2(f0.y, f0.x);
                    unsigned short e1 = fp8x2(f1.y, f1.x);
                    r[z] = (unsigned)e0 | ((unsigned)e1 << 16);
                }
                g_h0q[(size_t)(base + pt) * 4 + c16] = make_uint4(r[0], r[1], r[2], r[3]);
            }
        }
        __syncthreads();
    }

    // ---- reductions -> double atomics ----
    float sn = wsum(segnum), sd = wsum(segden);
    float* red = (float*)stg;
    if (lane == 0) { red[1024 + w] = sn; red[1040 + w] = sd; }
    red[tid] = s0; red[256 + tid] = s1; red[512 + tid] = q0; red[768 + tid] = q1;
    __syncthreads();
    if (tid == 0) {
        float a = 0.f, b = 0.f;
        for (int i = 0; i < 8; i++) { a += red[1024 + i]; b += red[1040 + i]; }
        atomicAdd(&g_acc[0], (double)a);
        atomicAdd(&g_acc[1], (double)b);
    }
    if (tid < 32) {
        float a0 = 0.f, a1 = 0.f, b0 = 0.f, b1 = 0.f;
        for (int g = 0; g < 8; g++) {
            a0 += red[g * 32 + tid];
            a1 += red[256 + g * 32 + tid];
            b0 += red[512 + g * 32 + tid];
            b1 += red[768 + g * 32 + tid];
        }
        atomicAdd(&g_sum[2 * tid],       (double)a0);
        atomicAdd(&g_sum[2 * tid + 1],   (double)a1);
        atomicAdd(&g_sumsq[2 * tid],     (double)b0);
        atomicAdd(&g_sumsq[2 * tid + 1], (double)b1);
    }
}

// ---------------- finalize BN affine (b1 cancels through BN) -------------------
__global__ void finalize_kernel(const float* __restrict__ gamma,
                                const float* __restrict__ beta,
                                const float* __restrict__ W2, int N)
{
    int ch = threadIdx.x;
    if (ch < CC) {
        double inv_n = 1.0 / (double)N;
        double m0  = g_sum[ch] * inv_n;
        double var = g_sumsq[ch] * inv_n - m0 * m0;
        float inv = rsqrtf((float)var + 1e-3f);
        float A = gamma[ch] * inv;
        float B = beta[ch] - (float)m0 * A;
        g_AB[ch]  = make_float2(A, B);
        g_W2p[ch] = make_float4(W2[3 * ch], W2[3 * ch + 1], W2[3 * ch + 2], 0.f);
    }
}

// ---------------- pass3: bias head + L1 + cosine losses ------------------------
__global__ __launch_bounds__(256, 4) void pass3_kernel(
    const float* __restrict__ coord, const int* __restrict__ instance,
    const float* __restrict__ cent, const float* __restrict__ b2,
    int N, int nt3)
{
    __shared__ unsigned stg[256 * 17];
    __shared__ float2 ABs[CC];
    __shared__ float4 W2s[CC];
    __shared__ float rb[24];
    const int tid = threadIdx.x;
    if (tid < CC) { ABs[tid] = g_AB[tid]; W2s[tid] = g_W2p[tid]; }
    const float b20 = b2[0], b21 = b2[1], b22 = b2[2];
    __syncthreads();

    float aL1 = 0.f, aCos = 0.f, aCnt = 0.f;

    for (int t = blockIdx.x; t < nt3; t += gridDim.x) {
        const int base = t * 256;
#pragma unroll
        for (int it = 0; it < 4; it++) {
            int idx = it * 256 + tid;
            int pt = idx >> 2, c16 = idx & 3;
            uint4 v = make_uint4(0, 0, 0, 0);
            if (base + pt < N) v = g_h0q[(size_t)(base + pt) * 4 + c16];
            // pitch-17 stage: NOT 16B-aligned -> scalar stores
            unsigned* d = stg + pt * 17 + c16 * 4;
            d[0] = v.x; d[1] = v.y; d[2] = v.z; d[3] = v.w;
        }
        __syncthreads();
        const int p = base + tid;
        float p0 = b20, p1 = b21, p2 = b22;
#pragma unroll
        for (int j = 0; j < 16; j++) {
            unsigned u = stg[tid * 17 + j];
            __half2 hlo = fp8_to_h2((unsigned short)(u & 0xffffu));
            __half2 hhi = fp8_to_h2((unsigned short)(u >> 16));
            float2 f01 = __half22float2(hlo);
            float2 f23 = __half22float2(hhi);
            int c = 4 * j;
            float hv[4] = {f01.x, f01.y, f23.x, f23.y};
#pragma unroll
            for (int z = 0; z < 4; z++) {
                float2 ab = ABs[c + z];
                float v = fmaxf(fmaf(hv[z], ab.x, ab.y), 0.f);
                float4 ww = W2s[c + z];
                p0 = fmaf(v, ww.x, p0);
                p1 = fmaf(v, ww.y, p1);
                p2 = fmaf(v, ww.z, p2);
            }
        }
        if (p < N) {
            int inst = instance[p];
            if (inst != -1) {
                float g0 = cent[3 * p]     - coord[3 * p];
                float g1 = cent[3 * p + 1] - coord[3 * p + 1];
                float g2 = cent[3 * p + 2] - coord[3 * p + 2];
                aL1 += fabsf(p0 - g0) + fabsf(p1 - g1) + fabsf(p2 - g2);
                float np = sqrtf(p0 * p0 + p1 * p1 + p2 * p2);
                float ng = sqrtf(g0 * g0 + g1 * g1 + g2 * g2);
                float dt = p0 * g0 + p1 * g1 + p2 * g2;
                aCos += -dt / ((np + 1e-8f) * (ng + 1e-8f));
                aCnt += 1.f;
            }
        }
        __syncthreads();
    }

    float a = wsum(aL1), b = wsum(aCos), c = wsum(aCnt);
    int wid = tid >> 5, lid = tid & 31;
    if (lid == 0) { rb[wid] = a; rb[8 + wid] = b; rb[16 + wid] = c; }
    __syncthreads();
    if (tid == 0) {
        float x = 0.f, y = 0.f, z = 0.f;
        for (int i = 0; i < 8; i++) { x += rb[i]; y += rb[8 + i]; z += rb[16 + i]; }
        atomicAdd(&g_acc[2], (double)x);
        atomicAdd(&g_acc[3], (double)y);
        atomicAdd(&g_acc[4], (double)z);
    }
}

// ---------------- final combine -------------------------------------------------
__global__ void out_kernel(float* __restrict__ out) {
    double seg   = g_acc[0] / g_acc[1];
    double denom = g_acc[4] + 1e-8;
    double l1    = g_acc[2] / denom;
    double cs    = g_acc[3] / denom;
    out[0] = (float)(seg + l1 + cs);
    out[1] = (float)seg;
    out[2] = (float)l1;
    out[3] = (float)cs;
}

// ---------------- launch ---------------------------------------------------------
extern "C" void kernel_launch(void* const* d_in, const int* in_sizes, int n_in,
                              void* d_out, int out_size)
{
    const float* feat     = (const float*)d_in[0];
    const float* coord    = (const float*)d_in[1];
    const int*   segment  = (const int*)d_in[2];
    const int*   instance = (const int*)d_in[3];
    const float* cent     = (const float*)d_in[4];
    const float* W1       = (const float*)d_in[5];
    // d_in[6] = b1 (cancels through BN)
    const float* gamma    = (const float*)d_in[7];
    const float* beta     = (const float*)d_in[8];
    const float* W2       = (const float*)d_in[9];
    const float* b2       = (const float*)d_in[10];
    const float* Wseg     = (const float*)d_in[11];
    const float* bseg     = (const float*)d_in[12];
    const float* cw       = (const float*)d_in[13];

    int N = in_sizes[0] / CC;
    if (N > NMAX) N = NMAX;
    int ntiles = (N + MT - 1) / MT;
    int nt3    = (N + 255) / 256;
    int grid1 = ntiles < 444 ? ntiles : 444;
    int grid3 = nt3 < 592 ? nt3 : 592;

    cudaFuncSetAttribute(pass1_kernel, cudaFuncAttributeMaxDynamicSharedMemorySize, SM1_BYTES);

    zero_kernel<<<1, 64>>>();
    pass1_kernel<<<grid1, 256, SM1_BYTES>>>(feat, segment, W1, Wseg, bseg, cw, N, ntiles);
    finalize_kernel<<<1, 64>>>(gamma, beta, W2, N);
    pass3_kernel<<<grid3, 256>>>(coord, instance, cent, b2, N, nt3);
    out_kernel<<<1, 1>>>((float*)d_out);
}